// round 8
// baseline (speedup 1.0000x reference)
#include <cuda_runtime.h>
#include <cuda_fp16.h>
#include <cstdint>

// Sinkhorn OT: B=1024, N=M=256, 100 iters, one CTA per batch, 256 threads.
// K and K^T both stored fp8 (e4m3, x16) in SMEM with 272B row pitch ->
// BOTH matvec passes are contiguous conflict-free LDS.128 row walks.
// fp16 HFMA2 accumulation (8 accs, chain 16); divides in fp32.
// Final cost recomputes exact fp32 K from C.

#define BATCH 1024
#define DIM 256
#define MAX_IT 100
#define EPS_DIV 1e-8f
#define KSC_K 16.0f
#define KSC_U 4.0f
#define KSC_V 256.0f
#define UNSC_KTU (1.0f/64.0f)      // 1/(16*4)
#define UNSC_KV  (1.0f/4096.0f)    // 1/(16*256)

#define PITCH 272                  // fp8 bytes per row (17*16 -> LDS.128 conflict-free)
#define OFF_K8   0
#define OFF_KT8  (256*PITCH)       // 69632
#define OFF_UH   (2*256*PITCH)     // 139264 : half[256] (u*4)
#define OFF_VH   (OFF_UH + 512)    // half[256] (v*256)
#define OFF_US   (OFF_VH + 512)
#define OFF_VS   (OFF_US + 1024)
#define OFF_AS   (OFF_VS + 1024)
#define OFF_BS   (OFF_AS + 1024)
#define OFF_RED  (OFF_BS + 1024)
#define SMEM_BYTES (OFF_RED + 64)

__device__ float g_partial[BATCH];

__device__ __forceinline__ __half2 H2(uint32_t w) {
    return *reinterpret_cast<__half2*>(&w);
}

// unpack 4 e4m3 bytes -> two half2 (elems 0,1 and 2,3)
__device__ __forceinline__ void fp8x4_to_h2(uint32_t w, uint32_t& lo2, uint32_t& hi2) {
    asm("{\n\t.reg .b16 l, h;\n\tmov.b32 {l, h}, %2;\n\t"
        "cvt.rn.f16x2.e4m3x2 %0, l;\n\tcvt.rn.f16x2.e4m3x2 %1, h;\n\t}"
        : "=r"(lo2), "=r"(hi2) : "r"(w));
}

// pack 4 floats -> 4 e4m3 bytes (elem0 in byte0)
__device__ __forceinline__ uint32_t f32x4_to_fp8(float f0, float f1, float f2, float f3) {
    uint16_t lo, hi;
    asm("cvt.rn.satfinite.e4m3x2.f32 %0, %1, %2;" : "=h"(lo) : "f"(f1), "f"(f0));
    asm("cvt.rn.satfinite.e4m3x2.f32 %0, %1, %2;" : "=h"(hi) : "f"(f3), "f"(f2));
    return (uint32_t)lo | ((uint32_t)hi << 16);
}

__device__ __forceinline__ float block_sum256(float val, float* red, int tid) {
    #pragma unroll
    for (int o = 16; o > 0; o >>= 1) val += __shfl_xor_sync(0xffffffffu, val, o);
    if ((tid & 31) == 0) red[tid >> 5] = val;
    __syncthreads();
    float t = 0.f;
    #pragma unroll
    for (int w = 0; w < 8; ++w) t += red[w];
    __syncthreads();
    return t;
}

// dot(row of fp8 matrix, vec of 256 halves), fp16 accumulation
__device__ __forceinline__ float row_dot_fp8(const unsigned char* row,
                                             const uint4* vec4) {
    const uint4* r4 = (const uint4*)row;
    __half2 a0 = __floats2half2_rn(0.f, 0.f);
    __half2 a1 = a0, a2 = a0, a3 = a0, a4 = a0, a5 = a0, a6 = a0, a7 = a0;
    #pragma unroll
    for (int j = 0; j < 16; ++j) {
        uint4 k  = r4[j];            // 16 fp8 elems
        uint4 va = vec4[2 * j];      // halves 16j..16j+7 (uniform broadcast)
        uint4 vb = vec4[2 * j + 1];  // halves 16j+8..16j+15
        uint32_t p, q;
        fp8x4_to_h2(k.x, p, q);
        a0 = __hfma2(H2(p), H2(va.x), a0);
        a1 = __hfma2(H2(q), H2(va.y), a1);
        fp8x4_to_h2(k.y, p, q);
        a2 = __hfma2(H2(p), H2(va.z), a2);
        a3 = __hfma2(H2(q), H2(va.w), a3);
        fp8x4_to_h2(k.z, p, q);
        a4 = __hfma2(H2(p), H2(vb.x), a4);
        a5 = __hfma2(H2(q), H2(vb.y), a5);
        fp8x4_to_h2(k.w, p, q);
        a6 = __hfma2(H2(p), H2(vb.z), a6);
        a7 = __hfma2(H2(q), H2(vb.w), a7);
    }
    float2 f0 = __half22float2(a0), f1 = __half22float2(a1);
    float2 f2 = __half22float2(a2), f3 = __half22float2(a3);
    float2 f4 = __half22float2(a4), f5 = __half22float2(a5);
    float2 f6 = __half22float2(a6), f7 = __half22float2(a7);
    return (((f0.x + f0.y) + (f1.x + f1.y)) + ((f2.x + f2.y) + (f3.x + f3.y)))
         + (((f4.x + f4.y) + (f5.x + f5.y)) + ((f6.x + f6.y) + (f7.x + f7.y)));
}

extern "C" __global__ void __launch_bounds__(256)
sinkhorn_kernel(const float* __restrict__ C,
                const float* __restrict__ mp,
                const float* __restrict__ mt)
{
    extern __shared__ unsigned char smem[];
    unsigned char* K8  = smem + OFF_K8;
    unsigned char* KT8 = smem + OFF_KT8;
    __half* u_h = (__half*)(smem + OFF_UH);
    __half* v_h = (__half*)(smem + OFF_VH);
    float* u_s = (float*)(smem + OFF_US);
    float* v_s = (float*)(smem + OFF_VS);
    float* a_s = (float*)(smem + OFF_AS);
    float* b_s = (float*)(smem + OFF_BS);
    float* red = (float*)(smem + OFF_RED);

    const int tid = threadIdx.x;
    const int b   = blockIdx.x;
    const float*  Cb = C + (size_t)b * (DIM * DIM);
    const float4* C4 = (const float4*)Cb;

    // ---- Phase 1: K -> fp8 SMEM row n; scatter K^T column n -------------
    {
        unsigned char* krow = K8 + tid * PITCH;
        #pragma unroll 4
        for (int j = 0; j < 64; ++j) {
            float4 c = C4[tid * 64 + j];
            uint32_t w = f32x4_to_fp8(__expf(-10.f * c.x) * KSC_K,
                                      __expf(-10.f * c.y) * KSC_K,
                                      __expf(-10.f * c.z) * KSC_K,
                                      __expf(-10.f * c.w) * KSC_K);
            *(uint32_t*)(krow + 4 * j) = w;
            int m = 4 * j;
            KT8[(m + 0) * PITCH + tid] = (unsigned char)(w);
            KT8[(m + 1) * PITCH + tid] = (unsigned char)(w >> 8);
            KT8[(m + 2) * PITCH + tid] = (unsigned char)(w >> 16);
            KT8[(m + 3) * PITCH + tid] = (unsigned char)(w >> 24);
        }
    }

    // ---- Phase 2: masses, init u ----------------------------------------
    float mpv = mp[b * DIM + tid];
    float mtv = mt[b * DIM + tid];
    __syncthreads();
    float smp = block_sum256(mpv, red, tid);
    float smt = block_sum256(mtv, red, tid);
    a_s[tid] = mpv / (smp + EPS_DIV);
    b_s[tid] = mtv / (smt + EPS_DIV);
    u_h[tid] = __float2half_rn(KSC_U);    // u = 1
    __syncthreads();

    const uint4* uh4 = (const uint4*)u_h;
    const uint4* vh4 = (const uint4*)v_h;
    const unsigned char* myKT = KT8 + tid * PITCH;
    const unsigned char* myK  = K8  + tid * PITCH;

    // ---- Phase 3: 100 iterations ----------------------------------------
    for (int it = 0; it < MAX_IT; ++it) {
        // Ktu[m] = dot(KT8 row m, u)
        float ktu = row_dot_fp8(myKT, uh4) * UNSC_KTU;
        float v = b_s[tid] / (ktu + EPS_DIV);
        v_s[tid] = v;
        v_h[tid] = __float2half_rn(v * KSC_V);
        __syncthreads();

        // Kv[n] = dot(K8 row n, v)
        float kv = row_dot_fp8(myK, vh4) * UNSC_KV;
        float u = a_s[tid] / (kv + EPS_DIV);
        u_s[tid] = u;
        u_h[tid] = __float2half_rn(u * KSC_U);
        __syncthreads();
    }

    // ---- Phase 4: cost with exact fp32 K --------------------------------
    float acc = 0.f;
    for (int i = tid; i < (DIM * DIM / 4); i += 256) {
        float4 c = C4[i];
        int r   = i >> 6;
        int col = (i & 63) << 2;
        float p = __expf(-10.f * c.x) * c.x * v_s[col + 0]
                + __expf(-10.f * c.y) * c.y * v_s[col + 1]
                + __expf(-10.f * c.z) * c.z * v_s[col + 2]
                + __expf(-10.f * c.w) * c.w * v_s[col + 3];
        acc = fmaf(u_s[r], p, acc);
    }
    float tot = block_sum256(acc, red, tid);
    if (tid == 0) g_partial[b] = tot;
}

extern "C" __global__ void __launch_bounds__(256)
reduce_kernel(float* __restrict__ out)
{
    __shared__ float red[8];
    int tid = threadIdx.x;
    float s = 0.f;
    #pragma unroll
    for (int i = 0; i < BATCH / 256; ++i) s += g_partial[tid + i * 256];
    #pragma unroll
    for (int o = 16; o > 0; o >>= 1) s += __shfl_xor_sync(0xffffffffu, s, o);
    if ((tid & 31) == 0) red[tid >> 5] = s;
    __syncthreads();
    if (tid == 0) {
        float t = 0.f;
        #pragma unroll
        for (int w = 0; w < 8; ++w) t += red[w];
        out[0] = t * (1.0f / (float)BATCH);
    }
}

extern "C" void kernel_launch(void* const* d_in, const int* in_sizes, int n_in,
                              void* d_out, int out_size)
{
    const float* C  = (const float*)d_in[0];
    const float* mp = (const float*)d_in[1];
    const float* mt = (const float*)d_in[2];

    cudaFuncSetAttribute(sinkhorn_kernel,
                         cudaFuncAttributeMaxDynamicSharedMemorySize, SMEM_BYTES);
    sinkhorn_kernel<<<BATCH, 256, SMEM_BYTES>>>(C, mp, mt);
    reduce_kernel<<<1, 256>>>((float*)d_out);
}

// round 9
// speedup vs baseline: 1.5267x; 1.5267x over previous
#include <cuda_runtime.h>
#include <cuda_fp16.h>
#include <cstdint>

// Sinkhorn OT: B=1024, N=M=256, 100 iters, one CTA/batch, 256 threads.
// K (x16 fp16) lives BOTH in SMEM (pitch 264 halves, for the column pass)
// and in 128 b32 registers per thread (its own row, for the row pass).
// Row pass does zero SMEM K traffic -> crossbar load halved vs R5.
// fp16 HFMA2 accumulation, fp32 divides; final cost uses exact fp32 K.

#define BATCH 1024
#define DIM 256
#define MAX_IT 100
#define EPS_DIV 1e-8f
#define KSC_K 16.0f
#define KSC_U 4.0f
#define KSC_V 256.0f
#define UNSC_KTU (1.0f/64.0f)
#define UNSC_KV  (1.0f/4096.0f)

#define SKH  264     // halves per K row (528 B)
#define SKH2 132     // half2 per K row

#define OFF_K    0
#define OFF_PART 135168
#define OFF_UH2  137216
#define OFF_VH   138240
#define OFF_US   138752
#define OFF_VS   139776
#define OFF_AS   140800
#define OFF_BS   141824
#define OFF_RED  142848
#define SMEM_BYTES 142912

__device__ float g_partial[BATCH];

__device__ __forceinline__ __half2 H2(uint32_t w) {
    return *reinterpret_cast<__half2*>(&w);
}

__device__ __forceinline__ float block_sum256(float val, float* red, int tid) {
    #pragma unroll
    for (int o = 16; o > 0; o >>= 1) val += __shfl_xor_sync(0xffffffffu, val, o);
    if ((tid & 31) == 0) red[tid >> 5] = val;
    __syncthreads();
    float t = 0.f;
    #pragma unroll
    for (int w = 0; w < 8; ++w) t += red[w];
    __syncthreads();
    return t;
}

extern "C" __global__ void __launch_bounds__(256, 1)
sinkhorn_kernel(const float* __restrict__ C,
                const float* __restrict__ mp,
                const float* __restrict__ mt)
{
    extern __shared__ unsigned char smem[];
    __half*  Kh   = (__half*)(smem + OFF_K);
    float2*  part = (float2*)(smem + OFF_PART);
    __half2* u_h2 = (__half2*)(smem + OFF_UH2);   // {u*4, u*4} per row
    __half*  v_h  = (__half*)(smem + OFF_VH);     // v*256 per col
    float*   u_s  = (float*)(smem + OFF_US);
    float*   v_s  = (float*)(smem + OFF_VS);
    float*   a_s  = (float*)(smem + OFF_AS);
    float*   b_s  = (float*)(smem + OFF_BS);
    float*   red  = (float*)(smem + OFF_RED);

    const int tid = threadIdx.x;
    const int b   = blockIdx.x;
    const float*  Cb = C + (size_t)b * (DIM * DIM);
    const float4* C4 = (const float4*)Cb;

    // ---- Phase 1a: K = exp(-10C)*16 -> fp16 SMEM (coalesced) ------------
    for (int i = tid; i < (DIM * DIM / 4); i += 256) {
        float4 c = C4[i];
        int r   = i >> 6;
        int col = (i & 63) << 2;
        __half2* dst = (__half2*)(Kh + r * SKH + col);
        dst[0] = __floats2half2_rn(__expf(-10.f * c.x) * KSC_K,
                                   __expf(-10.f * c.y) * KSC_K);
        dst[1] = __floats2half2_rn(__expf(-10.f * c.z) * KSC_K,
                                   __expf(-10.f * c.w) * KSC_K);
    }

    // ---- Phase 2: masses ------------------------------------------------
    float mpv = mp[b * DIM + tid];
    float mtv = mt[b * DIM + tid];
    __syncthreads();                 // Kh complete
    float smp = block_sum256(mpv, red, tid);
    float smt = block_sum256(mtv, red, tid);
    a_s[tid] = mpv / (smp + EPS_DIV);
    b_s[tid] = mtv / (smt + EPS_DIV);
    u_h2[tid] = __floats2half2_rn(KSC_U, KSC_U);   // u = 1

    // ---- Phase 1b: pull my K row into registers -------------------------
    uint32_t kreg[128];
    {
        const uint4* row4 = (const uint4*)(Kh + tid * SKH);  // 16B aligned
        #pragma unroll
        for (int j = 0; j < 32; ++j) {
            uint4 q = row4[j];
            kreg[4 * j + 0] = q.x;
            kreg[4 * j + 1] = q.y;
            kreg[4 * j + 2] = q.z;
            kreg[4 * j + 3] = q.w;
        }
    }
    __syncthreads();

    const __half2* Kc  = (const __half2*)Kh;
    const uint4*   uq4 = (const uint4*)u_h2;   // 4 rows per load (uniform)
    const uint4*   vh4 = (const uint4*)v_h;    // 8 cols per load (uniform)

    const int c = tid & 127;    // column-pair (cols 2c, 2c+1)
    const int h = tid >> 7;     // row half

    // ---- Phase 3: 100 iterations ---------------------------------------
    for (int it = 0; it < MAX_IT; ++it) {
        // -- col pass: Ktu over my column pair, my 128-row half ----------
        {
            __half2 a0 = __floats2half2_rn(0.f, 0.f);
            __half2 a1 = a0, a2 = a0, a3 = a0;
            const int base = h * 128;
            #pragma unroll 4
            for (int j = 0; j < 32; ++j) {
                int n = base + 4 * j;
                uint4 uu = uq4[(base >> 2) + j];
                a0 = __hfma2(Kc[(n + 0) * SKH2 + c], H2(uu.x), a0);
                a1 = __hfma2(Kc[(n + 1) * SKH2 + c], H2(uu.y), a1);
                a2 = __hfma2(Kc[(n + 2) * SKH2 + c], H2(uu.z), a2);
                a3 = __hfma2(Kc[(n + 3) * SKH2 + c], H2(uu.w), a3);
            }
            float2 f0 = __half22float2(a0), f1 = __half22float2(a1);
            float2 f2 = __half22float2(a2), f3 = __half22float2(a3);
            part[tid] = make_float2((f0.x + f1.x) + (f2.x + f3.x),
                                    (f0.y + f1.y) + (f2.y + f3.y));
        }
        __syncthreads();
        if (tid < 128) {
            float2 pa = part[tid];
            float2 pb = part[tid + 128];
            float v0 = b_s[2 * tid]     / ((pa.x + pb.x) * UNSC_KTU + EPS_DIV);
            float v1 = b_s[2 * tid + 1] / ((pa.y + pb.y) * UNSC_KTU + EPS_DIV);
            v_s[2 * tid]     = v0;
            v_s[2 * tid + 1] = v1;
            ((__half2*)v_h)[tid] = __floats2half2_rn(v0 * KSC_V, v1 * KSC_V);
        }
        __syncthreads();

        // -- row pass: Kv from REGISTERS (no SMEM K traffic) -------------
        {
            __half2 r0 = __floats2half2_rn(0.f, 0.f);
            __half2 r1 = r0, r2 = r0, r3 = r0, r4 = r0, r5 = r0, r6 = r0, r7 = r0;
            #pragma unroll
            for (int j = 0; j < 16; ++j) {
                uint4 va = vh4[2 * j];
                uint4 vb = vh4[2 * j + 1];
                r0 = __hfma2(H2(kreg[8 * j + 0]), H2(va.x), r0);
                r1 = __hfma2(H2(kreg[8 * j + 1]), H2(va.y), r1);
                r2 = __hfma2(H2(kreg[8 * j + 2]), H2(va.z), r2);
                r3 = __hfma2(H2(kreg[8 * j + 3]), H2(va.w), r3);
                r4 = __hfma2(H2(kreg[8 * j + 4]), H2(vb.x), r4);
                r5 = __hfma2(H2(kreg[8 * j + 5]), H2(vb.y), r5);
                r6 = __hfma2(H2(kreg[8 * j + 6]), H2(vb.z), r6);
                r7 = __hfma2(H2(kreg[8 * j + 7]), H2(vb.w), r7);
            }
            float2 g0 = __half22float2(r0), g1 = __half22float2(r1);
            float2 g2 = __half22float2(r2), g3 = __half22float2(r3);
            float2 g4 = __half22float2(r4), g5 = __half22float2(r5);
            float2 g6 = __half22float2(r6), g7 = __half22float2(r7);
            float kv = ((((g0.x + g0.y) + (g1.x + g1.y)) + ((g2.x + g2.y) + (g3.x + g3.y)))
                     +  (((g4.x + g4.y) + (g5.x + g5.y)) + ((g6.x + g6.y) + (g7.x + g7.y))))
                     * UNSC_KV;
            float u = a_s[tid] / (kv + EPS_DIV);
            u_s[tid] = u;
            u_h2[tid] = __floats2half2_rn(u * KSC_U, u * KSC_U);
        }
        __syncthreads();
    }

    // ---- Phase 4: cost with exact fp32 K --------------------------------
    float acc = 0.f;
    for (int i = tid; i < (DIM * DIM / 4); i += 256) {
        float4 cc = C4[i];
        int r   = i >> 6;
        int col = (i & 63) << 2;
        float p = __expf(-10.f * cc.x) * cc.x * v_s[col + 0]
                + __expf(-10.f * cc.y) * cc.y * v_s[col + 1]
                + __expf(-10.f * cc.z) * cc.z * v_s[col + 2]
                + __expf(-10.f * cc.w) * cc.w * v_s[col + 3];
        acc = fmaf(u_s[r], p, acc);
    }
    float tot = block_sum256(acc, red, tid);
    if (tid == 0) g_partial[b] = tot;
}

extern "C" __global__ void __launch_bounds__(256)
reduce_kernel(float* __restrict__ out)
{
    __shared__ float red[8];
    int tid = threadIdx.x;
    float s = 0.f;
    #pragma unroll
    for (int i = 0; i < BATCH / 256; ++i) s += g_partial[tid + i * 256];
    #pragma unroll
    for (int o = 16; o > 0; o >>= 1) s += __shfl_xor_sync(0xffffffffu, s, o);
    if ((tid & 31) == 0) red[tid >> 5] = s;
    __syncthreads();
    if (tid == 0) {
        float t = 0.f;
        #pragma unroll
        for (int w = 0; w < 8; ++w) t += red[w];
        out[0] = t * (1.0f / (float)BATCH);
    }
}

extern "C" void kernel_launch(void* const* d_in, const int* in_sizes, int n_in,
                              void* d_out, int out_size)
{
    const float* C  = (const float*)d_in[0];
    const float* mp = (const float*)d_in[1];
    const float* mt = (const float*)d_in[2];

    cudaFuncSetAttribute(sinkhorn_kernel,
                         cudaFuncAttributeMaxDynamicSharedMemorySize, SMEM_BYTES);
    sinkhorn_kernel<<<BATCH, 256, SMEM_BYTES>>>(C, mp, mt);
    reduce_kernel<<<1, 256>>>((float*)d_out);
}

// round 11
// speedup vs baseline: 1.5905x; 1.0418x over previous
#include <cuda_runtime.h>
#include <cuda_fp16.h>
#include <cstdint>

// Sinkhorn OT: B=1024, N=M=256, 100 iters, one CTA/batch, 256 threads.
// Setup: K (x16 fp16) built in SMEM -> each thread copies its row into
// 128 b32 registers -> SMEM buffer is overwritten with K^T (scatter from
// registers). Iterations: row pass (Kv) entirely from registers; col pass
// (K^T u) is a contiguous conflict-free LDS.128 walk over K^T rows with a
// full 256-dot per thread (no partial combine). 2 barriers/iter.
// fp16 HFMA2 accumulation (chains <= 16), fp32 divides; final cost exact fp32.

#define BATCH 1024
#define DIM 256
#define MAX_IT 100
#define EPS_DIV 1e-8f
#define KSC_K 16.0f
#define KSC_U 4.0f
#define KSC_V 256.0f
#define UNSC_KTU (1.0f/64.0f)
#define UNSC_KV  (1.0f/4096.0f)

#define SKH  264     // halves per row (528 B) - conflict-free LDS.128 pitch
#define OFF_K    0           // K, later K^T (135168 B)
#define OFF_UH   135168      // half[256]  u*4
#define OFF_VH   135680      // half[256]  v*256
#define OFF_US   136192
#define OFF_VS   137216
#define OFF_AS   138240
#define OFF_BS   139264
#define OFF_RED  140288
#define SMEM_BYTES 140352

__device__ float g_partial[BATCH];

__device__ __forceinline__ __half2 H2(uint32_t w) {
    return *reinterpret_cast<__half2*>(&w);
}

__device__ __forceinline__ float block_sum256(float val, float* red, int tid) {
    #pragma unroll
    for (int o = 16; o > 0; o >>= 1) val += __shfl_xor_sync(0xffffffffu, val, o);
    if ((tid & 31) == 0) red[tid >> 5] = val;
    __syncthreads();
    float t = 0.f;
    #pragma unroll
    for (int w = 0; w < 8; ++w) t += red[w];
    __syncthreads();
    return t;
}

extern "C" __global__ void __launch_bounds__(256, 1)
sinkhorn_kernel(const float* __restrict__ C,
                const float* __restrict__ mp,
                const float* __restrict__ mt)
{
    extern __shared__ unsigned char smem[];
    __half* Kh  = (__half*)(smem + OFF_K);
    __half* u_h = (__half*)(smem + OFF_UH);
    __half* v_h = (__half*)(smem + OFF_VH);
    float*  u_s = (float*)(smem + OFF_US);
    float*  v_s = (float*)(smem + OFF_VS);
    float*  a_s = (float*)(smem + OFF_AS);
    float*  b_s = (float*)(smem + OFF_BS);
    float*  red = (float*)(smem + OFF_RED);

    const int tid = threadIdx.x;
    const int b   = blockIdx.x;
    const float*  Cb = C + (size_t)b * (DIM * DIM);
    const float4* C4 = (const float4*)Cb;

    // ---- Phase 1a: K = exp(-10C)*16 -> fp16 SMEM (coalesced) ------------
    for (int i = tid; i < (DIM * DIM / 4); i += 256) {
        float4 c = C4[i];
        int r   = i >> 6;
        int col = (i & 63) << 2;
        __half2* dst = (__half2*)(Kh + r * SKH + col);
        dst[0] = __floats2half2_rn(__expf(-10.f * c.x) * KSC_K,
                                   __expf(-10.f * c.y) * KSC_K);
        dst[1] = __floats2half2_rn(__expf(-10.f * c.z) * KSC_K,
                                   __expf(-10.f * c.w) * KSC_K);
    }

    // masses (overlap with K build)
    float mpv = mp[b * DIM + tid];
    float mtv = mt[b * DIM + tid];
    __syncthreads();                          // K complete

    // ---- Phase 1b: pull my K row (256 halves) into 128 registers --------
    uint32_t kreg[128];
    {
        const uint4* row4 = (const uint4*)(Kh + tid * SKH);
        #pragma unroll
        for (int j = 0; j < 32; ++j) {
            uint4 q = row4[j];
            kreg[4 * j + 0] = q.x;
            kreg[4 * j + 1] = q.y;
            kreg[4 * j + 2] = q.z;
            kreg[4 * j + 3] = q.w;
        }
    }
    __syncthreads();                          // everyone holds their row

    // ---- Phase 1c: overwrite SMEM with K^T (scatter from registers) -----
    {
        #pragma unroll 8
        for (int j = 0; j < 128; ++j) {
            __half2 p = H2(kreg[j]);
            Kh[(2 * j)     * SKH + tid] = __low2half(p);
            Kh[(2 * j + 1) * SKH + tid] = __high2half(p);
        }
    }

    // ---- Phase 2: normalize masses, init u ------------------------------
    float smp = block_sum256(mpv, red, tid);  // includes __syncthreads
    float smt = block_sum256(mtv, red, tid);
    a_s[tid] = mpv / (smp + EPS_DIV);
    b_s[tid] = mtv / (smt + EPS_DIV);
    u_h[tid] = __float2half_rn(KSC_U);        // u = 1
    __syncthreads();

    const uint4* kt4_base = (const uint4*)(Kh + tid * SKH);  // my K^T row
    const uint4* uh4 = (const uint4*)u_h;     // uniform broadcast
    const uint4* vh4 = (const uint4*)v_h;

    // ---- Phase 3: 100 iterations ----------------------------------------
    for (int it = 0; it < MAX_IT; ++it) {
        // -- col pass: Ktu[m=tid] = dot(K^T row m, u), LDS.128 walk -------
        {
            __half2 A[16];
            #pragma unroll
            for (int i = 0; i < 16; ++i) A[i] = __floats2half2_rn(0.f, 0.f);
            #pragma unroll
            for (int j = 0; j < 32; ++j) {
                uint4 k  = kt4_base[j];
                uint4 uu = uh4[j];
                const int g = (j & 3) * 4;
                A[g + 0] = __hfma2(H2(k.x), H2(uu.x), A[g + 0]);
                A[g + 1] = __hfma2(H2(k.y), H2(uu.y), A[g + 1]);
                A[g + 2] = __hfma2(H2(k.z), H2(uu.z), A[g + 2]);
                A[g + 3] = __hfma2(H2(k.w), H2(uu.w), A[g + 3]);
            }
            float s = 0.f;
            #pragma unroll
            for (int i = 0; i < 16; ++i) {
                float2 f = __half22float2(A[i]);
                s += f.x + f.y;
            }
            float v = b_s[tid] / (s * UNSC_KTU + EPS_DIV);
            v_s[tid] = v;
            v_h[tid] = __float2half_rn(v * KSC_V);
        }
        __syncthreads();

        // -- row pass: Kv[n=tid] from REGISTERS ---------------------------
        {
            __half2 r0 = __floats2half2_rn(0.f, 0.f);
            __half2 r1 = r0, r2 = r0, r3 = r0, r4 = r0, r5 = r0, r6 = r0, r7 = r0;
            #pragma unroll
            for (int j = 0; j < 16; ++j) {
                uint4 va = vh4[2 * j];
                uint4 vb = vh4[2 * j + 1];
                r0 = __hfma2(H2(kreg[8 * j + 0]), H2(va.x), r0);
                r1 = __hfma2(H2(kreg[8 * j + 1]), H2(va.y), r1);
                r2 = __hfma2(H2(kreg[8 * j + 2]), H2(va.z), r2);
                r3 = __hfma2(H2(kreg[8 * j + 3]), H2(va.w), r3);
                r4 = __hfma2(H2(kreg[8 * j + 4]), H2(vb.x), r4);
                r5 = __hfma2(H2(kreg[8 * j + 5]), H2(vb.y), r5);
                r6 = __hfma2(H2(kreg[8 * j + 6]), H2(vb.z), r6);
                r7 = __hfma2(H2(kreg[8 * j + 7]), H2(vb.w), r7);
            }
            float2 g0 = __half22float2(r0), g1 = __half22float2(r1);
            float2 g2 = __half22float2(r2), g3 = __half22float2(r3);
            float2 g4 = __half22float2(r4), g5 = __half22float2(r5);
            float2 g6 = __half22float2(r6), g7 = __half22float2(r7);
            float kv = ((((g0.x + g0.y) + (g1.x + g1.y)) + ((g2.x + g2.y) + (g3.x + g3.y)))
                     +  (((g4.x + g4.y) + (g5.x + g5.y)) + ((g6.x + g6.y) + (g7.x + g7.y))))
                     * UNSC_KV;
            float u = a_s[tid] / (kv + EPS_DIV);
            u_s[tid] = u;
            u_h[tid] = __float2half_rn(u * KSC_U);
        }
        __syncthreads();
    }

    // ---- Phase 4: cost with exact fp32 K --------------------------------
    float acc = 0.f;
    for (int i = tid; i < (DIM * DIM / 4); i += 256) {
        float4 cc = C4[i];
        int r   = i >> 6;
        int col = (i & 63) << 2;
        float p = __expf(-10.f * cc.x) * cc.x * v_s[col + 0]
                + __expf(-10.f * cc.y) * cc.y * v_s[col + 1]
                + __expf(-10.f * cc.z) * cc.z * v_s[col + 2]
                + __expf(-10.f * cc.w) * cc.w * v_s[col + 3];
        acc = fmaf(u_s[r], p, acc);
    }
    float tot = block_sum256(acc, red, tid);
    if (tid == 0) g_partial[b] = tot;
}

extern "C" __global__ void __launch_bounds__(256)
reduce_kernel(float* __restrict__ out)
{
    __shared__ float red[8];
    int tid = threadIdx.x;
    float s = 0.f;
    #pragma unroll
    for (int i = 0; i < BATCH / 256; ++i) s += g_partial[tid + i * 256];
    #pragma unroll
    for (int o = 16; o > 0; o >>= 1) s += __shfl_xor_sync(0xffffffffu, s, o);
    if ((tid & 31) == 0) red[tid >> 5] = s;
    __syncthreads();
    if (tid == 0) {
        float t = 0.f;
        #pragma unroll
        for (int w = 0; w < 8; ++w) t += red[w];
        out[0] = t * (1.0f / (float)BATCH);
    }
}

extern "C" void kernel_launch(void* const* d_in, const int* in_sizes, int n_in,
                              void* d_out, int out_size)
{
    const float* C  = (const float*)d_in[0];
    const float* mp = (const float*)d_in[1];
    const float* mt = (const float*)d_in[2];

    cudaFuncSetAttribute(sinkhorn_kernel,
                         cudaFuncAttributeMaxDynamicSharedMemorySize, SMEM_BYTES);
    sinkhorn_kernel<<<BATCH, 256, SMEM_BYTES>>>(C, mp, mt);
    reduce_kernel<<<1, 256>>>((float*)d_out);
}

// round 12
// speedup vs baseline: 1.6745x; 1.0528x over previous
#include <cuda_runtime.h>
#include <cuda_fp16.h>
#include <cstdint>

// Sinkhorn OT: B=1024, N=M=256, <=100 iters, one CTA/batch, 256 threads.
// K rows in registers (row pass), K^T in SMEM (col pass, LDS.128 walk).
// fp16 HFMA2 accumulation, fp32 divides; final cost exact fp32.
// NEW: exact fixed-point early exit — when the fp16 iterate u_h is
// bitwise-unchanged across an iteration, all remaining iterations are
// no-ops; exit test fused into the iteration barrier (__syncthreads_and).

#define BATCH 1024
#define DIM 256
#define MAX_IT 100
#define EPS_DIV 1e-8f
#define KSC_K 16.0f
#define KSC_U 4.0f
#define KSC_V 256.0f
#define UNSC_KTU (1.0f/64.0f)
#define UNSC_KV  (1.0f/4096.0f)

#define SKH  264     // halves per row (528 B) - conflict-free LDS.128 pitch
#define OFF_K    0           // K, later K^T (135168 B)
#define OFF_UH   135168      // half[256]  u*4
#define OFF_VH   135680      // half[256]  v*256
#define OFF_US   136192
#define OFF_VS   137216
#define OFF_AS   138240
#define OFF_BS   139264
#define OFF_RED  140288
#define SMEM_BYTES 140352

__device__ float g_partial[BATCH];

__device__ __forceinline__ __half2 H2(uint32_t w) {
    return *reinterpret_cast<__half2*>(&w);
}

__device__ __forceinline__ float block_sum256(float val, float* red, int tid) {
    #pragma unroll
    for (int o = 16; o > 0; o >>= 1) val += __shfl_xor_sync(0xffffffffu, val, o);
    if ((tid & 31) == 0) red[tid >> 5] = val;
    __syncthreads();
    float t = 0.f;
    #pragma unroll
    for (int w = 0; w < 8; ++w) t += red[w];
    __syncthreads();
    return t;
}

extern "C" __global__ void __launch_bounds__(256, 1)
sinkhorn_kernel(const float* __restrict__ C,
                const float* __restrict__ mp,
                const float* __restrict__ mt)
{
    extern __shared__ unsigned char smem[];
    __half* Kh  = (__half*)(smem + OFF_K);
    __half* u_h = (__half*)(smem + OFF_UH);
    __half* v_h = (__half*)(smem + OFF_VH);
    float*  u_s = (float*)(smem + OFF_US);
    float*  v_s = (float*)(smem + OFF_VS);
    float*  a_s = (float*)(smem + OFF_AS);
    float*  b_s = (float*)(smem + OFF_BS);
    float*  red = (float*)(smem + OFF_RED);

    const int tid = threadIdx.x;
    const int b   = blockIdx.x;
    const float*  Cb = C + (size_t)b * (DIM * DIM);
    const float4* C4 = (const float4*)Cb;

    // ---- Phase 1a: K = exp(-10C)*16 -> fp16 SMEM (coalesced) ------------
    for (int i = tid; i < (DIM * DIM / 4); i += 256) {
        float4 c = C4[i];
        int r   = i >> 6;
        int col = (i & 63) << 2;
        __half2* dst = (__half2*)(Kh + r * SKH + col);
        dst[0] = __floats2half2_rn(__expf(-10.f * c.x) * KSC_K,
                                   __expf(-10.f * c.y) * KSC_K);
        dst[1] = __floats2half2_rn(__expf(-10.f * c.z) * KSC_K,
                                   __expf(-10.f * c.w) * KSC_K);
    }

    float mpv = mp[b * DIM + tid];
    float mtv = mt[b * DIM + tid];
    __syncthreads();                          // K complete

    // ---- Phase 1b: my K row (256 halves) -> 128 registers ---------------
    uint32_t kreg[128];
    {
        const uint4* row4 = (const uint4*)(Kh + tid * SKH);
        #pragma unroll
        for (int j = 0; j < 32; ++j) {
            uint4 q = row4[j];
            kreg[4 * j + 0] = q.x;
            kreg[4 * j + 1] = q.y;
            kreg[4 * j + 2] = q.z;
            kreg[4 * j + 3] = q.w;
        }
    }
    __syncthreads();                          // all rows in regs

    // ---- Phase 1c: overwrite SMEM with K^T (scatter from registers) -----
    #pragma unroll 8
    for (int j = 0; j < 128; ++j) {
        __half2 p = H2(kreg[j]);
        Kh[(2 * j)     * SKH + tid] = __low2half(p);
        Kh[(2 * j + 1) * SKH + tid] = __high2half(p);
    }

    // ---- Phase 2: normalize masses, init u ------------------------------
    float smp = block_sum256(mpv, red, tid);  // includes barriers
    float smt = block_sum256(mtv, red, tid);
    a_s[tid] = mpv / (smp + EPS_DIV);
    b_s[tid] = mtv / (smt + EPS_DIV);
    u_h[tid] = __float2half_rn(KSC_U);        // u = 1
    __syncthreads();

    const uint4* kt4_base = (const uint4*)(Kh + tid * SKH);  // my K^T row
    const uint4* uh4 = (const uint4*)u_h;
    const uint4* vh4 = (const uint4*)v_h;

    unsigned short uprev = __half_as_ushort(__float2half_rn(KSC_U));

    // ---- Phase 3: up to 100 iterations, exact fixed-point exit ----------
    for (int it = 0; it < MAX_IT; ++it) {
        // -- col pass: Ktu[m=tid] = dot(K^T row m, u) ---------------------
        {
            __half2 A[16];
            #pragma unroll
            for (int i = 0; i < 16; ++i) A[i] = __floats2half2_rn(0.f, 0.f);
            #pragma unroll
            for (int j = 0; j < 32; ++j) {
                uint4 k  = kt4_base[j];
                uint4 uu = uh4[j];
                const int g = (j & 3) * 4;
                A[g + 0] = __hfma2(H2(k.x), H2(uu.x), A[g + 0]);
                A[g + 1] = __hfma2(H2(k.y), H2(uu.y), A[g + 1]);
                A[g + 2] = __hfma2(H2(k.z), H2(uu.z), A[g + 2]);
                A[g + 3] = __hfma2(H2(k.w), H2(uu.w), A[g + 3]);
            }
            float s = 0.f;
            #pragma unroll
            for (int i = 0; i < 16; ++i) {
                float2 f = __half22float2(A[i]);
                s += f.x + f.y;
            }
            float v = b_s[tid] / (s * UNSC_KTU + EPS_DIV);
            v_s[tid] = v;
            v_h[tid] = __float2half_rn(v * KSC_V);
        }
        __syncthreads();

        // -- row pass: Kv[n=tid] from REGISTERS ---------------------------
        unsigned short ubits;
        {
            __half2 r0 = __floats2half2_rn(0.f, 0.f);
            __half2 r1 = r0, r2 = r0, r3 = r0, r4 = r0, r5 = r0, r6 = r0, r7 = r0;
            #pragma unroll
            for (int j = 0; j < 16; ++j) {
                uint4 va = vh4[2 * j];
                uint4 vb = vh4[2 * j + 1];
                r0 = __hfma2(H2(kreg[8 * j + 0]), H2(va.x), r0);
                r1 = __hfma2(H2(kreg[8 * j + 1]), H2(va.y), r1);
                r2 = __hfma2(H2(kreg[8 * j + 2]), H2(va.z), r2);
                r3 = __hfma2(H2(kreg[8 * j + 3]), H2(va.w), r3);
                r4 = __hfma2(H2(kreg[8 * j + 4]), H2(vb.x), r4);
                r5 = __hfma2(H2(kreg[8 * j + 5]), H2(vb.y), r5);
                r6 = __hfma2(H2(kreg[8 * j + 6]), H2(vb.z), r6);
                r7 = __hfma2(H2(kreg[8 * j + 7]), H2(vb.w), r7);
            }
            float2 g0 = __half22float2(r0), g1 = __half22float2(r1);
            float2 g2 = __half22float2(r2), g3 = __half22float2(r3);
            float2 g4 = __half22float2(r4), g5 = __half22float2(r5);
            float2 g6 = __half22float2(r6), g7 = __half22float2(r7);
            float kv = ((((g0.x + g0.y) + (g1.x + g1.y)) + ((g2.x + g2.y) + (g3.x + g3.y)))
                     +  (((g4.x + g4.y) + (g5.x + g5.y)) + ((g6.x + g6.y) + (g7.x + g7.y))))
                     * UNSC_KV;
            float u = a_s[tid] / (kv + EPS_DIV);
            u_s[tid] = u;
            __half uh = __float2half_rn(u * KSC_U);
            u_h[tid] = uh;
            ubits = __half_as_ushort(uh);
        }
        // Fused barrier + fixed-point test: if EVERY thread's fp16 iterate
        // is bit-identical to last iteration, remaining iters are no-ops.
        if (__syncthreads_and((int)(ubits == uprev))) break;
        uprev = ubits;
    }

    // ---- Phase 4: cost with exact fp32 K --------------------------------
    float acc = 0.f;
    for (int i = tid; i < (DIM * DIM / 4); i += 256) {
        float4 cc = C4[i];
        int r   = i >> 6;
        int col = (i & 63) << 2;
        float p = __expf(-10.f * cc.x) * cc.x * v_s[col + 0]
                + __expf(-10.f * cc.y) * cc.y * v_s[col + 1]
                + __expf(-10.f * cc.z) * cc.z * v_s[col + 2]
                + __expf(-10.f * cc.w) * cc.w * v_s[col + 3];
        acc = fmaf(u_s[r], p, acc);
    }
    float tot = block_sum256(acc, red, tid);
    if (tid == 0) g_partial[b] = tot;
}

extern "C" __global__ void __launch_bounds__(256)
reduce_kernel(float* __restrict__ out)
{
    __shared__ float red[8];
    int tid = threadIdx.x;
    float s = 0.f;
    #pragma unroll
    for (int i = 0; i < BATCH / 256; ++i) s += g_partial[tid + i * 256];
    #pragma unroll
    for (int o = 16; o > 0; o >>= 1) s += __shfl_xor_sync(0xffffffffu, s, o);
    if ((tid & 31) == 0) red[tid >> 5] = s;
    __syncthreads();
    if (tid == 0) {
        float t = 0.f;
        #pragma unroll
        for (int w = 0; w < 8; ++w) t += red[w];
        out[0] = t * (1.0f / (float)BATCH);
    }
}

extern "C" void kernel_launch(void* const* d_in, const int* in_sizes, int n_in,
                              void* d_out, int out_size)
{
    const float* C  = (const float*)d_in[0];
    const float* mp = (const float*)d_in[1];
    const float* mt = (const float*)d_in[2];

    cudaFuncSetAttribute(sinkhorn_kernel,
                         cudaFuncAttributeMaxDynamicSharedMemorySize, SMEM_BYTES);
    sinkhorn_kernel<<<BATCH, 256, SMEM_BYTES>>>(C, mp, mt);
    reduce_kernel<<<1, 256>>>((float*)d_out);
}

// round 14
// speedup vs baseline: 6.2439x; 3.7287x over previous
#include <cuda_runtime.h>
#include <cuda_fp16.h>
#include <cstdint>

// Sinkhorn OT: B=1024, N=M=256, <=100 iters, one CTA/batch, 512 threads.
// Thread pair (2i, 2i+1) owns row i: lane h=tid&1 handles element half
// [128h, 128h+128). Row pass from 64 regs/thread; col pass over K^T in
// SMEM (pitch 544B, half-offset 272B -> conflict-free paired LDS.128).
// Pair partials combined with shfl_xor(1). 2 barriers/iter.
// Exit: whole-state period-2 bit test (parity-matched) == bit-exact
// equivalent of running all 100 iters. Final cost exact fp32.

#define BATCH 1024
#define DIM 256
#define MAX_IT 100
#define EPS_DIV 1e-8f
#define KSC_K 16.0f
#define KSC_U 4.0f
#define KSC_V 256.0f
#define UNSC_KTU (1.0f/64.0f)
#define UNSC_KV  (1.0f/4096.0f)
#define NT 512

#define ROW_B 544            // bytes per row (136 words; 136%32=8)
#define SEG_B 272            // byte offset of half-1 (68 words; 68%32=4)
#define OFF_UH  139264       // 256*544 ; half[256] u*4
#define OFF_VH  (OFF_UH + 512)
#define OFF_US  (OFF_VH + 512)
#define OFF_VS  (OFF_US + 1024)
#define OFF_AS  (OFF_VS + 1024)
#define OFF_BS  (OFF_AS + 1024)
#define OFF_RED (OFF_BS + 1024)   // float[16]
#define SMEM_BYTES (OFF_RED + 64)

__device__ float g_partial[BATCH];

__device__ __forceinline__ __half2 H2(uint32_t w) {
    return *reinterpret_cast<__half2*>(&w);
}

__device__ __forceinline__ float block_sum512(float val, float* red, int tid) {
    #pragma unroll
    for (int o = 16; o > 0; o >>= 1) val += __shfl_xor_sync(0xffffffffu, val, o);
    if ((tid & 31) == 0) red[tid >> 5] = val;
    __syncthreads();
    float t = 0.f;
    #pragma unroll
    for (int w = 0; w < 16; ++w) t += red[w];
    __syncthreads();
    return t;
}

extern "C" __global__ void __launch_bounds__(NT, 1)
sinkhorn_kernel(const float* __restrict__ C,
                const float* __restrict__ mp,
                const float* __restrict__ mt)
{
    extern __shared__ unsigned char smem[];
    __half* u_h = (__half*)(smem + OFF_UH);
    __half* v_h = (__half*)(smem + OFF_VH);
    float*  u_s = (float*)(smem + OFF_US);
    float*  v_s = (float*)(smem + OFF_VS);
    float*  a_s = (float*)(smem + OFF_AS);
    float*  b_s = (float*)(smem + OFF_BS);
    float*  red = (float*)(smem + OFF_RED);

    const int tid = threadIdx.x;
    const int r   = tid >> 1;    // my row (0..255)
    const int h   = tid & 1;     // my half of the row
    const int b   = blockIdx.x;
    const float*  Cb = C + (size_t)b * (DIM * DIM);
    const float4* C4 = (const float4*)Cb;

    // ---- Phase 1a: K = exp(-10C)*16 -> fp16 SMEM (padded layout) --------
    for (int i = tid; i < (DIM * DIM / 4); i += NT) {
        float4 c = C4[i];
        int row = i >> 6;
        int col = (i & 63) << 2;
        int seg = col >> 7;
        int win = col & 127;
        __half2* dst = (__half2*)(smem + row * ROW_B + seg * SEG_B + win * 2);
        dst[0] = __floats2half2_rn(__expf(-10.f * c.x) * KSC_K,
                                   __expf(-10.f * c.y) * KSC_K);
        dst[1] = __floats2half2_rn(__expf(-10.f * c.z) * KSC_K,
                                   __expf(-10.f * c.w) * KSC_K);
    }
    float mpv = (tid < 256) ? mp[b * DIM + tid] : 0.f;
    float mtv = (tid < 256) ? mt[b * DIM + tid] : 0.f;
    __syncthreads();                          // K complete

    // ---- Phase 1b: my half-row (128 halves) -> 64 registers -------------
    uint32_t kreg[64];
    {
        const uint4* row4 = (const uint4*)(smem + r * ROW_B + h * SEG_B);
        #pragma unroll
        for (int j = 0; j < 16; ++j) {
            uint4 q = row4[j];
            kreg[4 * j + 0] = q.x;
            kreg[4 * j + 1] = q.y;
            kreg[4 * j + 2] = q.z;
            kreg[4 * j + 3] = q.w;
        }
    }
    __syncthreads();                          // all of K held in regs

    // ---- Phase 1c: overwrite SMEM with K^T (scatter from registers) -----
    {
        const int seg_r = r >> 7;
        const int win_r = (r & 127) * 2;
        #pragma unroll 8
        for (int j = 0; j < 64; ++j) {
            __half2 p = H2(kreg[j]);
            int c0 = 128 * h + 2 * j;         // K column = K^T row
            *(__half*)(smem + c0 * ROW_B + seg_r * SEG_B + win_r) = __low2half(p);
            *(__half*)(smem + (c0 + 1) * ROW_B + seg_r * SEG_B + win_r) = __high2half(p);
        }
    }

    // ---- Phase 2: normalize masses, init u (barriers fence the scatter) -
    float smp = block_sum512(mpv, red, tid);
    float smt = block_sum512(mtv, red, tid);
    if (tid < 256) {
        a_s[tid] = mpv / (smp + EPS_DIV);
        b_s[tid] = mtv / (smt + EPS_DIV);
        u_h[tid] = __float2half_rn(KSC_U);    // u = 1
    }
    __syncthreads();

    const uint4* kt4 = (const uint4*)(smem + r * ROW_B + h * SEG_B); // K^T row r, my half
    const uint4* uh4 = (const uint4*)u_h;
    const uint4* vh4 = (const uint4*)v_h;

    unsigned short prev1 = __half_as_ushort(__float2half_rn(KSC_U));
    unsigned short prev2 = 0xFFFFu;           // u^(-1): invalid

    // ---- Phase 3: <=100 iterations, exact period-2 exit -----------------
    for (int it = 0; it < MAX_IT; ++it) {
        // -- col pass: Ktu[r] partial over my half, pair-combined ---------
        float v;
        {
            __half2 A0 = __floats2half2_rn(0.f, 0.f);
            __half2 A1 = A0, A2 = A0, A3 = A0, A4 = A0, A5 = A0, A6 = A0, A7 = A0;
            #pragma unroll
            for (int j = 0; j < 16; j += 2) {
                uint4 k0 = kt4[j];
                uint4 uu0 = uh4[16 * h + j];
                A0 = __hfma2(H2(k0.x), H2(uu0.x), A0);
                A1 = __hfma2(H2(k0.y), H2(uu0.y), A1);
                A2 = __hfma2(H2(k0.z), H2(uu0.z), A2);
                A3 = __hfma2(H2(k0.w), H2(uu0.w), A3);
                uint4 k1 = kt4[j + 1];
                uint4 uu1 = uh4[16 * h + j + 1];
                A4 = __hfma2(H2(k1.x), H2(uu1.x), A4);
                A5 = __hfma2(H2(k1.y), H2(uu1.y), A5);
                A6 = __hfma2(H2(k1.z), H2(uu1.z), A6);
                A7 = __hfma2(H2(k1.w), H2(uu1.w), A7);
            }
            float2 f0 = __half22float2(A0), f1 = __half22float2(A1);
            float2 f2 = __half22float2(A2), f3 = __half22float2(A3);
            float2 f4 = __half22float2(A4), f5 = __half22float2(A5);
            float2 f6 = __half22float2(A6), f7 = __half22float2(A7);
            float s = (((f0.x + f0.y) + (f1.x + f1.y)) + ((f2.x + f2.y) + (f3.x + f3.y)))
                    + (((f4.x + f4.y) + (f5.x + f5.y)) + ((f6.x + f6.y) + (f7.x + f7.y)));
            s += __shfl_xor_sync(0xffffffffu, s, 1);      // pair combine
            v = b_s[r] / (s * UNSC_KTU + EPS_DIV);
            if (h == 0) {
                v_s[r] = v;
                v_h[r] = __float2half_rn(v * KSC_V);
            }
        }
        __syncthreads();

        // -- row pass: Kv[r] partial from registers, pair-combined --------
        unsigned short ubits;
        {
            __half2 R0 = __floats2half2_rn(0.f, 0.f);
            __half2 R1 = R0, R2 = R0, R3 = R0, R4 = R0, R5 = R0, R6 = R0, R7 = R0;
            #pragma unroll
            for (int j = 0; j < 16; j += 2) {
                uint4 vv0 = vh4[16 * h + j];
                R0 = __hfma2(H2(kreg[4 * j + 0]), H2(vv0.x), R0);
                R1 = __hfma2(H2(kreg[4 * j + 1]), H2(vv0.y), R1);
                R2 = __hfma2(H2(kreg[4 * j + 2]), H2(vv0.z), R2);
                R3 = __hfma2(H2(kreg[4 * j + 3]), H2(vv0.w), R3);
                uint4 vv1 = vh4[16 * h + j + 1];
                R4 = __hfma2(H2(kreg[4 * j + 4]), H2(vv1.x), R4);
                R5 = __hfma2(H2(kreg[4 * j + 5]), H2(vv1.y), R5);
                R6 = __hfma2(H2(kreg[4 * j + 6]), H2(vv1.z), R6);
                R7 = __hfma2(H2(kreg[4 * j + 7]), H2(vv1.w), R7);
            }
            float2 g0 = __half22float2(R0), g1 = __half22float2(R1);
            float2 g2 = __half22float2(R2), g3 = __half22float2(R3);
            float2 g4 = __half22float2(R4), g5 = __half22float2(R5);
            float2 g6 = __half22float2(R6), g7 = __half22float2(R7);
            float kv = (((g0.x + g0.y) + (g1.x + g1.y)) + ((g2.x + g2.y) + (g3.x + g3.y)))
                     + (((g4.x + g4.y) + (g5.x + g5.y)) + ((g6.x + g6.y) + (g7.x + g7.y)));
            kv += __shfl_xor_sync(0xffffffffu, kv, 1);    // pair combine
            float u = a_s[r] / (kv * UNSC_KV + EPS_DIV);
            __half uh = __float2half_rn(u * KSC_U);
            ubits = __half_as_ushort(uh);
            if (h == 0) {
                u_s[r] = u;
                u_h[r] = uh;
            }
        }
        // Whole-state period-2 test (parity-matched -> bit-exact skip).
        int conv = __syncthreads_and((int)(ubits == prev2));
        if (conv && (it & 1)) break;
        prev2 = prev1;
        prev1 = ubits;
    }

    // ---- Phase 4: cost with exact fp32 K --------------------------------
    float acc = 0.f;
    #pragma unroll 4
    for (int i = tid; i < (DIM * DIM / 4); i += NT) {
        float4 cc = C4[i];
        int rr  = i >> 6;
        int col = (i & 63) << 2;
        float p = __expf(-10.f * cc.x) * cc.x * v_s[col + 0]
                + __expf(-10.f * cc.y) * cc.y * v_s[col + 1]
                + __expf(-10.f * cc.z) * cc.z * v_s[col + 2]
                + __expf(-10.f * cc.w) * cc.w * v_s[col + 3];
        acc = fmaf(u_s[rr], p, acc);
    }
    float tot = block_sum512(acc, red, tid);
    if (tid == 0) g_partial[b] = tot;
}

extern "C" __global__ void __launch_bounds__(256)
reduce_kernel(float* __restrict__ out)
{
    __shared__ float red[8];
    int tid = threadIdx.x;
    float s = 0.f;
    #pragma unroll
    for (int i = 0; i < BATCH / 256; ++i) s += g_partial[tid + i * 256];
    #pragma unroll
    for (int o = 16; o > 0; o >>= 1) s += __shfl_xor_sync(0xffffffffu, s, o);
    if ((tid & 31) == 0) red[tid >> 5] = s;
    __syncthreads();
    if (tid == 0) {
        float t = 0.f;
        #pragma unroll
        for (int w = 0; w < 8; ++w) t += red[w];
        out[0] = t * (1.0f / (float)BATCH);
    }
}

extern "C" void kernel_launch(void* const* d_in, const int* in_sizes, int n_in,
                              void* d_out, int out_size)
{
    const float* C  = (const float*)d_in[0];
    const float* mp = (const float*)d_in[1];
    const float* mt = (const float*)d_in[2];

    cudaFuncSetAttribute(sinkhorn_kernel,
                         cudaFuncAttributeMaxDynamicSharedMemorySize, SMEM_BYTES);
    sinkhorn_kernel<<<BATCH, NT, SMEM_BYTES>>>(C, mp, mt);
    reduce_kernel<<<1, 256>>>((float*)d_out);
}

// round 15
// speedup vs baseline: 6.4766x; 1.0373x over previous
#include <cuda_runtime.h>
#include <cuda_fp16.h>
#include <cstdint>

// Sinkhorn OT: B=1024, N=M=256, <=100 iters, one CTA/batch, 512 threads.
// Thread pair (2i, 2i+1) owns row i; lane h=tid&1 handles half [128h,128h+128).
// Row pass from 64 regs/thread; col pass over K^T in SMEM (pitch 544B,
// conflict-free paired LDS.128). Period-2 bitwise exit (bit-exact skip).
// Phase 4 NEW: cost computed from registers only — C is reconstructed as
// -0.1*ln(K16/16) via MUFU log, eliminating the second 256MB read of C.

#define BATCH 1024
#define DIM 256
#define MAX_IT 100
#define EPS_DIV 1e-8f
#define KSC_K 16.0f
#define KSC_U 4.0f
#define KSC_V 256.0f
#define UNSC_KTU (1.0f/64.0f)
#define UNSC_KV  (1.0f/4096.0f)
#define NT 512
#define LN16 2.7725887222397812f

#define ROW_B 544            // bytes per row (136 words; 136%32=8)
#define SEG_B 272            // byte offset of half-1 (68 words; 68%32=4)
#define OFF_UH  139264       // 256*544 ; half[256] u*4
#define OFF_VH  (OFF_UH + 512)
#define OFF_US  (OFF_VH + 512)
#define OFF_VS  (OFF_US + 1024)
#define OFF_AS  (OFF_VS + 1024)
#define OFF_BS  (OFF_AS + 1024)
#define OFF_RED (OFF_BS + 1024)   // float[16]
#define SMEM_BYTES (OFF_RED + 64)

__device__ float g_partial[BATCH];

__device__ __forceinline__ __half2 H2(uint32_t w) {
    return *reinterpret_cast<__half2*>(&w);
}

__device__ __forceinline__ float block_sum512(float val, float* red, int tid) {
    #pragma unroll
    for (int o = 16; o > 0; o >>= 1) val += __shfl_xor_sync(0xffffffffu, val, o);
    if ((tid & 31) == 0) red[tid >> 5] = val;
    __syncthreads();
    float t = 0.f;
    #pragma unroll
    for (int w = 0; w < 16; ++w) t += red[w];
    __syncthreads();
    return t;
}

extern "C" __global__ void __launch_bounds__(NT, 1)
sinkhorn_kernel(const float* __restrict__ C,
                const float* __restrict__ mp,
                const float* __restrict__ mt)
{
    extern __shared__ unsigned char smem[];
    __half* u_h = (__half*)(smem + OFF_UH);
    __half* v_h = (__half*)(smem + OFF_VH);
    float*  u_s = (float*)(smem + OFF_US);
    float*  v_s = (float*)(smem + OFF_VS);
    float*  a_s = (float*)(smem + OFF_AS);
    float*  b_s = (float*)(smem + OFF_BS);
    float*  red = (float*)(smem + OFF_RED);

    const int tid = threadIdx.x;
    const int r   = tid >> 1;    // my row (0..255)
    const int h   = tid & 1;     // my half of the row
    const int b   = blockIdx.x;
    const float*  Cb = C + (size_t)b * (DIM * DIM);
    const float4* C4 = (const float4*)Cb;

    // ---- Phase 1a: K = exp(-10C)*16 -> fp16 SMEM (padded layout) --------
    for (int i = tid; i < (DIM * DIM / 4); i += NT) {
        float4 c = C4[i];
        int row = i >> 6;
        int col = (i & 63) << 2;
        int seg = col >> 7;
        int win = col & 127;
        __half2* dst = (__half2*)(smem + row * ROW_B + seg * SEG_B + win * 2);
        dst[0] = __floats2half2_rn(__expf(-10.f * c.x) * KSC_K,
                                   __expf(-10.f * c.y) * KSC_K);
        dst[1] = __floats2half2_rn(__expf(-10.f * c.z) * KSC_K,
                                   __expf(-10.f * c.w) * KSC_K);
    }
    float mpv = (tid < 256) ? mp[b * DIM + tid] : 0.f;
    float mtv = (tid < 256) ? mt[b * DIM + tid] : 0.f;
    __syncthreads();                          // K complete

    // ---- Phase 1b: my half-row (128 halves) -> 64 registers -------------
    uint32_t kreg[64];
    {
        const uint4* row4 = (const uint4*)(smem + r * ROW_B + h * SEG_B);
        #pragma unroll
        for (int j = 0; j < 16; ++j) {
            uint4 q = row4[j];
            kreg[4 * j + 0] = q.x;
            kreg[4 * j + 1] = q.y;
            kreg[4 * j + 2] = q.z;
            kreg[4 * j + 3] = q.w;
        }
    }
    __syncthreads();                          // all of K held in regs

    // ---- Phase 1c: overwrite SMEM with K^T (scatter from registers) -----
    {
        const int seg_r = r >> 7;
        const int win_r = (r & 127) * 2;
        #pragma unroll 8
        for (int j = 0; j < 64; ++j) {
            __half2 p = H2(kreg[j]);
            int c0 = 128 * h + 2 * j;         // K column = K^T row
            *(__half*)(smem + c0 * ROW_B + seg_r * SEG_B + win_r) = __low2half(p);
            *(__half*)(smem + (c0 + 1) * ROW_B + seg_r * SEG_B + win_r) = __high2half(p);
        }
    }

    // ---- Phase 2: normalize masses, init u (barriers fence the scatter) -
    float smp = block_sum512(mpv, red, tid);
    float smt = block_sum512(mtv, red, tid);
    if (tid < 256) {
        a_s[tid] = mpv / (smp + EPS_DIV);
        b_s[tid] = mtv / (smt + EPS_DIV);
        u_h[tid] = __float2half_rn(KSC_U);    // u = 1
    }
    __syncthreads();

    const uint4* kt4 = (const uint4*)(smem + r * ROW_B + h * SEG_B); // K^T row r, my half
    const uint4* uh4 = (const uint4*)u_h;
    const uint4* vh4 = (const uint4*)v_h;

    unsigned short prev1 = __half_as_ushort(__float2half_rn(KSC_U));
    unsigned short prev2 = 0xFFFFu;           // u^(-1): invalid

    // ---- Phase 3: <=100 iterations, exact period-2 exit -----------------
    for (int it = 0; it < MAX_IT; ++it) {
        // -- col pass: Ktu[r] partial over my half, pair-combined ---------
        float v;
        {
            __half2 A0 = __floats2half2_rn(0.f, 0.f);
            __half2 A1 = A0, A2 = A0, A3 = A0, A4 = A0, A5 = A0, A6 = A0, A7 = A0;
            #pragma unroll
            for (int j = 0; j < 16; j += 2) {
                uint4 k0 = kt4[j];
                uint4 uu0 = uh4[16 * h + j];
                A0 = __hfma2(H2(k0.x), H2(uu0.x), A0);
                A1 = __hfma2(H2(k0.y), H2(uu0.y), A1);
                A2 = __hfma2(H2(k0.z), H2(uu0.z), A2);
                A3 = __hfma2(H2(k0.w), H2(uu0.w), A3);
                uint4 k1 = kt4[j + 1];
                uint4 uu1 = uh4[16 * h + j + 1];
                A4 = __hfma2(H2(k1.x), H2(uu1.x), A4);
                A5 = __hfma2(H2(k1.y), H2(uu1.y), A5);
                A6 = __hfma2(H2(k1.z), H2(uu1.z), A6);
                A7 = __hfma2(H2(k1.w), H2(uu1.w), A7);
            }
            float2 f0 = __half22float2(A0), f1 = __half22float2(A1);
            float2 f2 = __half22float2(A2), f3 = __half22float2(A3);
            float2 f4 = __half22float2(A4), f5 = __half22float2(A5);
            float2 f6 = __half22float2(A6), f7 = __half22float2(A7);
            float s = (((f0.x + f0.y) + (f1.x + f1.y)) + ((f2.x + f2.y) + (f3.x + f3.y)))
                    + (((f4.x + f4.y) + (f5.x + f5.y)) + ((f6.x + f6.y) + (f7.x + f7.y)));
            s += __shfl_xor_sync(0xffffffffu, s, 1);      // pair combine
            v = b_s[r] / (s * UNSC_KTU + EPS_DIV);
            if (h == 0) {
                v_s[r] = v;
                v_h[r] = __float2half_rn(v * KSC_V);
            }
        }
        __syncthreads();

        // -- row pass: Kv[r] partial from registers, pair-combined --------
        unsigned short ubits;
        {
            __half2 R0 = __floats2half2_rn(0.f, 0.f);
            __half2 R1 = R0, R2 = R0, R3 = R0, R4 = R0, R5 = R0, R6 = R0, R7 = R0;
            #pragma unroll
            for (int j = 0; j < 16; j += 2) {
                uint4 vv0 = vh4[16 * h + j];
                R0 = __hfma2(H2(kreg[4 * j + 0]), H2(vv0.x), R0);
                R1 = __hfma2(H2(kreg[4 * j + 1]), H2(vv0.y), R1);
                R2 = __hfma2(H2(kreg[4 * j + 2]), H2(vv0.z), R2);
                R3 = __hfma2(H2(kreg[4 * j + 3]), H2(vv0.w), R3);
                uint4 vv1 = vh4[16 * h + j + 1];
                R4 = __hfma2(H2(kreg[4 * j + 4]), H2(vv1.x), R4);
                R5 = __hfma2(H2(kreg[4 * j + 5]), H2(vv1.y), R5);
                R6 = __hfma2(H2(kreg[4 * j + 6]), H2(vv1.z), R6);
                R7 = __hfma2(H2(kreg[4 * j + 7]), H2(vv1.w), R7);
            }
            float2 g0 = __half22float2(R0), g1 = __half22float2(R1);
            float2 g2 = __half22float2(R2), g3 = __half22float2(R3);
            float2 g4 = __half22float2(R4), g5 = __half22float2(R5);
            float2 g6 = __half22float2(R6), g7 = __half22float2(R7);
            float kv = (((g0.x + g0.y) + (g1.x + g1.y)) + ((g2.x + g2.y) + (g3.x + g3.y)))
                     + (((g4.x + g4.y) + (g5.x + g5.y)) + ((g6.x + g6.y) + (g7.x + g7.y)));
            kv += __shfl_xor_sync(0xffffffffu, kv, 1);    // pair combine
            float u = a_s[r] / (kv * UNSC_KV + EPS_DIV);
            __half uh = __float2half_rn(u * KSC_U);
            ubits = __half_as_ushort(uh);
            if (h == 0) {
                u_s[r] = u;
                u_h[r] = uh;
            }
        }
        // Whole-state period-2 test (parity-matched -> bit-exact skip).
        int conv = __syncthreads_and((int)(ubits == prev2));
        if (conv && (it & 1)) break;
        prev2 = prev1;
        prev1 = ubits;
    }

    // ---- Phase 4: cost from REGISTERS — no second read of C -------------
    // term = u * (t/16) * (-0.1*(ln t - ln16)) * v,  t = kreg fp16 = 16*K.
    float acc = 0.f;
    {
        const float* vsh = v_s + 128 * h;
        #pragma unroll
        for (int j = 0; j < 32; ++j) {
            float4 vv = *(const float4*)(vsh + 4 * j);
            float2 kA = __half22float2(H2(kreg[2 * j]));
            float2 kB = __half22float2(H2(kreg[2 * j + 1]));
            acc = fmaf(kA.x * (__logf(kA.x) - LN16), vv.x, acc);
            acc = fmaf(kA.y * (__logf(kA.y) - LN16), vv.y, acc);
            acc = fmaf(kB.x * (__logf(kB.x) - LN16), vv.z, acc);
            acc = fmaf(kB.y * (__logf(kB.y) - LN16), vv.w, acc);
        }
        acc *= u_s[r] * (-0.1f / 16.0f);
    }
    float tot = block_sum512(acc, red, tid);
    if (tid == 0) g_partial[b] = tot;
}

extern "C" __global__ void __launch_bounds__(256)
reduce_kernel(float* __restrict__ out)
{
    __shared__ float red[8];
    int tid = threadIdx.x;
    float s = 0.f;
    #pragma unroll
    for (int i = 0; i < BATCH / 256; ++i) s += g_partial[tid + i * 256];
    #pragma unroll
    for (int o = 16; o > 0; o >>= 1) s += __shfl_xor_sync(0xffffffffu, s, o);
    if ((tid & 31) == 0) red[tid >> 5] = s;
    __syncthreads();
    if (tid == 0) {
        float t = 0.f;
        #pragma unroll
        for (int w = 0; w < 8; ++w) t += red[w];
        out[0] = t * (1.0f / (float)BATCH);
    }
}

extern "C" void kernel_launch(void* const* d_in, const int* in_sizes, int n_in,
                              void* d_out, int out_size)
{
    const float* C  = (const float*)d_in[0];
    const float* mp = (const float*)d_in[1];
    const float* mt = (const float*)d_in[2];

    cudaFuncSetAttribute(sinkhorn_kernel,
                         cudaFuncAttributeMaxDynamicSharedMemorySize, SMEM_BYTES);
    sinkhorn_kernel<<<BATCH, NT, SMEM_BYTES>>>(C, mp, mt);
    reduce_kernel<<<1, 256>>>((float*)d_out);
}